// round 14
// baseline (speedup 1.0000x reference)
#include <cuda_runtime.h>
#include <cuda_bf16.h>
#include <cstdint>

#define BD 4
#define CD 256
#define HD 56
#define WD 56
#define GD 16
#define GCD 16
#define POSN (BD*HD*WD)   // 12544
#define IN1 2112
#define OUT1 96
#define OWD 112
#define KHALF 1056        // IN1/2 (k units)
#define N2 192

// Scratch (device globals)
__device__ float    g_desc[(size_t)IN1 * POSN];      // [feature][pos] ~106 MB
__device__ float    g_rp[2ull * POSN * OUT1];        // split-K partials (pre-BN)
__device__ uint32_t g_w1ph[(size_t)(IN1/2) * OUT1];  // bf16x2-packed hi, [kp][n]
__device__ uint32_t g_w1pl[(size_t)(IN1/2) * OUT1];  // bf16x2-packed lo residual
__device__ float    g_w23h[(size_t)OUT1 * N2];       // tf32 split for gemm2
__device__ float    g_w23l[(size_t)OUT1 * N2];
__device__ float    g_wab[(size_t)POSN * N2];        // wa | wb

// ---------------------------------------------------------------------------
// helpers
// ---------------------------------------------------------------------------
__device__ __forceinline__ uint32_t f2tf32(float f) {
    uint32_t r;
    asm("cvt.rna.tf32.f32 %0, %1;" : "=r"(r) : "f"(f));
    return r;
}
__device__ __forceinline__ void mma_tf32(float* c, const uint32_t* a, const uint32_t* b) {
    asm volatile(
        "mma.sync.aligned.m16n8k8.row.col.f32.tf32.tf32.f32 "
        "{%0,%1,%2,%3}, {%4,%5,%6,%7}, {%8,%9}, {%0,%1,%2,%3};"
        : "+f"(c[0]), "+f"(c[1]), "+f"(c[2]), "+f"(c[3])
        : "r"(a[0]), "r"(a[1]), "r"(a[2]), "r"(a[3]), "r"(b[0]), "r"(b[1]));
}
__device__ __forceinline__ void mma_bf16(float* c, const uint32_t* a, const uint32_t* b) {
    asm volatile(
        "mma.sync.aligned.m16n8k16.row.col.f32.bf16.bf16.f32 "
        "{%0,%1,%2,%3}, {%4,%5,%6,%7}, {%8,%9}, {%0,%1,%2,%3};"
        : "+f"(c[0]), "+f"(c[1]), "+f"(c[2]), "+f"(c[3])
        : "r"(a[0]), "r"(a[1]), "r"(a[2]), "r"(a[3]), "r"(b[0]), "r"(b[1]));
}
__device__ __forceinline__ uint32_t packbf(float klo, float khi) {
    uint32_t r;
    asm("cvt.rn.bf16x2.f32 %0, %1, %2;" : "=r"(r) : "f"(khi), "f"(klo));
    return r;
}
__device__ __forceinline__ float bfround(float v) {
    return __bfloat162float(__float2bfloat16(v));
}

// ---------------------------------------------------------------------------
// K0a: pack w1 -> bf16x2 hi/lo, [kp][n]  (kp = k/2) — plain k order (R11)
// ---------------------------------------------------------------------------
__global__ __launch_bounds__(256) void w1pack_kernel(const float* __restrict__ w1) {
    int idx = blockIdx.x * 256 + threadIdx.x;
    if (idx >= (IN1/2) * OUT1) return;
    int n  = idx % OUT1;
    int kp = idx / OUT1;
    float v0 = w1[(unsigned)n * IN1 + 2*kp];
    float v1 = w1[(unsigned)n * IN1 + 2*kp + 1];
    float h0 = bfround(v0), h1 = bfround(v1);
    g_w1ph[idx] = packbf(h0, h1);
    g_w1pl[idx] = packbf(v0 - h0, v1 - h1);
}

// ---------------------------------------------------------------------------
// K0b: pre-split [w2|w3] -> [k][n] tf32 hi/lo (gemm2, unchanged)
// ---------------------------------------------------------------------------
__global__ __launch_bounds__(256) void w23split_kernel(
    const float* __restrict__ w2, const float* __restrict__ w3) {
    int idx = blockIdx.x * 256 + threadIdx.x;
    if (idx >= OUT1 * N2) return;
    int n = idx % N2;
    int k = idx / N2;
    float v = (n < OUT1) ? w2[(unsigned)n * OUT1 + k]
                         : w3[(unsigned)(n - OUT1) * OUT1 + k];
    float h = __uint_as_float(f2tf32(v));
    g_w23h[idx] = h;
    g_w23l[idx] = __uint_as_float(f2tf32(v - h));
}

// ---------------------------------------------------------------------------
// Scrambled-unfold taps (matches actual reference)
// ---------------------------------------------------------------------------
__device__ __forceinline__ void load_taps(const float* __restrict__ x,
                                          int b, int g, int h2,
                                          float (*xs)[3][3][58], int tid) {
    const unsigned cbase = (unsigned)(b*CD + g*GCD);
    for (int idx = tid; idx < GCD * 9 * 58; idx += 128) {
        int wp = idx % 58;
        int t  = idx / 58;
        int kh = t % 3;
        int kw = (t / 3) % 3;
        int gc = t / 9;
        int m  = kw * 56 + h2;
        int hh = m / 3 + kh - 1;
        int ww = wp - 1;
        float v = 0.f;
        if (hh >= 0 && hh < HD && ww >= 0 && ww < WD)
            v = x[((cbase + gc)*HD + hh)*WD + ww];
        xs[gc][kw][kh][wp] = v;
    }
}

// ---------------------------------------------------------------------------
// K1: descriptor build (unchanged, proven)
// ---------------------------------------------------------------------------
__global__ __launch_bounds__(128) void desc_kernel(const float* __restrict__ x) {
    const int g = blockIdx.x, h2 = blockIdx.y, b = blockIdx.z;
    __shared__ float xs[GCD][3][3][58];

    const int tid = threadIdx.x;
    load_taps(x, b, g, h2, xs, tid);
    __syncthreads();

    const int jv0 = h2 % 3, jv1 = (56 + h2) % 3, jv2 = (112 + h2) % 3;
    const unsigned posBase = (unsigned)(b*HD + h2)*WD;

    for (int it = tid; it < GCD * WD; it += 128) {
        int w  = it % WD;
        int gc = it / WD;
        float T[3][3];
        #pragma unroll
        for (int kh = 0; kh < 3; kh++) {
            T[kh][0] = xs[gc][0][kh][w + jv0];
            T[kh][1] = xs[gc][1][kh][w + jv1];
            T[kh][2] = xs[gc][2][kh][w + jv2];
        }
        unsigned f2 = (unsigned)(576 + g*48 + gc*3);
        unsigned f3 = (unsigned)(1344 + g*48 + gc*3);
        #pragma unroll
        for (int kw = 0; kw < 3; kw++) {
            float m = fmaxf(T[0][kw], fmaxf(T[1][kw], T[2][kw]));
            g_desc[(f2 + kw)*POSN + posBase + w] = m;
        }
        #pragma unroll
        for (int kh = 0; kh < 3; kh++) {
            float m = fmaxf(T[kh][0], fmaxf(T[kh][1], T[kh][2]));
            g_desc[(f3 + kh)*POSN + posBase + w] = m;
        }
    }

    const int jvv[3] = {jv0, jv1, jv2};
    for (int it = tid; it < 4 * WD; it += 128) {
        int w  = it % WD;
        int jc = it / WD;
        unsigned f1 = (unsigned)(g*36 + jc*9);
        #pragma unroll
        for (int kh = 0; kh < 3; kh++) {
            #pragma unroll
            for (int kw = 0; kw < 3; kw++) {
                int wp = w + jvv[kw];
                float m = xs[jc][kw][kh][wp];
                m = fmaxf(m, xs[jc + 4 ][kw][kh][wp]);
                m = fmaxf(m, xs[jc + 8 ][kw][kh][wp]);
                m = fmaxf(m, xs[jc + 12][kw][kh][wp]);
                g_desc[(f1 + kh*3 + kw)*POSN + posBase + w] = m;
            }
        }
    }
}

// ---------------------------------------------------------------------------
// K2: GEMM1 3xBF16 m16n8k16, NOW DOUBLE-BUFFERED (1 sync/chunk, LDG hidden).
// BM=64, BN=96, chunk = 8 kp (16 k). 256 thr = 8 warps (2m x 4n).
// ---------------------------------------------------------------------------
#define GBM 64
#define APR 72
#define BPR 104

__global__ __launch_bounds__(256) void gemm_tc_kernel() {
    __shared__ uint32_t Aph[2][8][APR], Apl[2][8][APR];   // 2*2*2304 B
    __shared__ uint32_t Bph[2][8][BPR], Bpl[2][8][BPR];   // 2*2*3328 B  => ~22.5 KB

    const int tid  = threadIdx.x;
    const int warp = tid >> 5;
    const int lane = tid & 31;
    const int wm = warp >> 2;          // 0..1 (m)
    const int wn = warp & 3;           // 0..3 (n)
    const int ar = lane >> 2;          // 0..7
    const int ac = lane & 3;           // 0..3
    const unsigned row0 = blockIdx.x * GBM;
    const int khalf = blockIdx.y;
    const unsigned kbase = khalf * KHALF;          // k units
    const unsigned kpbase = kbase >> 1;            // kp units

    float c[2][3][4];
    #pragma unroll
    for (int mt = 0; mt < 2; mt++)
        #pragma unroll
        for (int nt = 0; nt < 3; nt++)
            #pragma unroll
            for (int q = 0; q < 4; q++) c[mt][nt][q] = 0.f;

    // A prefetch mapping: thread -> (kp row 0..7, m pair)
    const int akp = tid >> 5;          // 0..7
    const int am2 = lane * 2;          // 0..62
    // B prefetch mapping: threads 0..191 -> (kp 0..7, n quad 0..23)
    const bool bact = tid < 192;
    const int bkp = tid / 24;          // 0..7
    const int bn4 = (tid % 24) * 4;    // 0,4,...,92

    float2 av0, av1;
    uint4 bvh, bvl;

    // --- prefetch chunk 0 ---
    {
        unsigned krow = kbase + 2*akp;
        av0 = *reinterpret_cast<const float2*>(&g_desc[(size_t)krow*POSN + row0 + am2]);
        av1 = *reinterpret_cast<const float2*>(&g_desc[(size_t)(krow+1)*POSN + row0 + am2]);
        if (bact) {
            const unsigned base = kpbase * OUT1 + bkp*OUT1 + bn4;
            bvh = *reinterpret_cast<const uint4*>(&g_w1ph[base]);
            bvl = *reinterpret_cast<const uint4*>(&g_w1pl[base]);
        }
    }
    // --- stage chunk 0 into buf 0 ---
    {
        float h00 = bfround(av0.x), h10 = bfround(av1.x);
        float h01 = bfround(av0.y), h11 = bfround(av1.y);
        *reinterpret_cast<uint2*>(&Aph[0][akp][am2]) =
            make_uint2(packbf(h00, h10), packbf(h01, h11));
        *reinterpret_cast<uint2*>(&Apl[0][akp][am2]) =
            make_uint2(packbf(av0.x - h00, av1.x - h10),
                       packbf(av0.y - h01, av1.y - h11));
        if (bact) {
            *reinterpret_cast<uint4*>(&Bph[0][bkp][bn4]) = bvh;
            *reinterpret_cast<uint4*>(&Bpl[0][bkp][bn4]) = bvl;
        }
    }
    __syncthreads();

    int cur = 0;
    for (int k0 = 0; k0 < KHALF; k0 += 16) {
        const bool more = (k0 + 16 < KHALF);
        // prefetch next chunk (LDG issued before compute; consumed after)
        if (more) {
            unsigned krow = kbase + k0 + 16 + 2*akp;
            av0 = *reinterpret_cast<const float2*>(&g_desc[(size_t)krow*POSN + row0 + am2]);
            av1 = *reinterpret_cast<const float2*>(&g_desc[(size_t)(krow+1)*POSN + row0 + am2]);
            if (bact) {
                const unsigned base = (kpbase + ((k0 + 16) >> 1))*OUT1 + bkp*OUT1 + bn4;
                bvh = *reinterpret_cast<const uint4*>(&g_w1ph[base]);
                bvl = *reinterpret_cast<const uint4*>(&g_w1pl[base]);
            }
        }

        // compute from buf[cur]
        uint32_t ah[2][4], al[2][4];
        #pragma unroll
        for (int mt = 0; mt < 2; mt++) {
            int mrow = wm*32 + mt*16 + ar;
            ah[mt][0] = Aph[cur][ac  ][mrow];   ah[mt][1] = Aph[cur][ac  ][mrow+8];
            ah[mt][2] = Aph[cur][ac+4][mrow];   ah[mt][3] = Aph[cur][ac+4][mrow+8];
            al[mt][0] = Apl[cur][ac  ][mrow];   al[mt][1] = Apl[cur][ac  ][mrow+8];
            al[mt][2] = Apl[cur][ac+4][mrow];   al[mt][3] = Apl[cur][ac+4][mrow+8];
        }
        uint32_t bh[3][2], bl[3][2];
        #pragma unroll
        for (int nt = 0; nt < 3; nt++) {
            int n = wn*24 + nt*8 + ar;
            bh[nt][0] = Bph[cur][ac][n];  bh[nt][1] = Bph[cur][ac+4][n];
            bl[nt][0] = Bpl[cur][ac][n];  bl[nt][1] = Bpl[cur][ac+4][n];
        }
        #pragma unroll
        for (int mt = 0; mt < 2; mt++)
            #pragma unroll
            for (int nt = 0; nt < 3; nt++) {
                mma_bf16(c[mt][nt], ah[mt], bl[nt]);   // hi x lo
                mma_bf16(c[mt][nt], al[mt], bh[nt]);   // lo x hi
                mma_bf16(c[mt][nt], ah[mt], bh[nt]);   // hi x hi
            }

        // stage next chunk into buf[cur^1]
        if (more) {
            float h00 = bfround(av0.x), h10 = bfround(av1.x);
            float h01 = bfround(av0.y), h11 = bfround(av1.y);
            *reinterpret_cast<uint2*>(&Aph[cur^1][akp][am2]) =
                make_uint2(packbf(h00, h10), packbf(h01, h11));
            *reinterpret_cast<uint2*>(&Apl[cur^1][akp][am2]) =
                make_uint2(packbf(av0.x - h00, av1.x - h10),
                           packbf(av0.y - h01, av1.y - h11));
            if (bact) {
                *reinterpret_cast<uint4*>(&Bph[cur^1][bkp][bn4]) = bvh;
                *reinterpret_cast<uint4*>(&Bpl[cur^1][bkp][bn4]) = bvl;
            }
        }
        __syncthreads();
        cur ^= 1;
    }

    float* rp = &g_rp[(size_t)khalf * POSN * OUT1];
    #pragma unroll
    for (int nt = 0; nt < 3; nt++) {
        int n0 = wn*24 + nt*8 + 2*ac;
        #pragma unroll
        for (int mt = 0; mt < 2; mt++) {
            unsigned m0 = row0 + wm*32 + mt*16 + ar;
            *reinterpret_cast<float2*>(&rp[m0*OUT1 + n0]) =
                make_float2(c[mt][nt][0], c[mt][nt][1]);
            *reinterpret_cast<float2*>(&rp[(m0+8)*OUT1 + n0]) =
                make_float2(c[mt][nt][2], c[mt][nt][3]);
        }
    }
}

// ---------------------------------------------------------------------------
// K2b: GEMM2 (tf32x3, unchanged): wab = relu(BN(rp0+rp1)) @ w23 + bias
// ---------------------------------------------------------------------------
#define GBK 16
#define A2STR 72
#define B2STR 200

__global__ __launch_bounds__(256) void gemm2_kernel(
    const float* __restrict__ gamma, const float* __restrict__ beta,
    const float* __restrict__ mean,  const float* __restrict__ var,
    const float* __restrict__ b2,    const float* __restrict__ b3)
{
    __shared__ float A2h[GBK][A2STR], A2l[GBK][A2STR];
    __shared__ float B2h[GBK][B2STR], B2l[GBK][B2STR];
    __shared__ float sS[OUT1], sB[OUT1];

    const int tid  = threadIdx.x;
    const int warp = tid >> 5;
    const int lane = tid & 31;
    const int wm = warp >> 2;
    const int wn = warp & 3;
    const int ar = lane >> 2;
    const int ac = lane & 3;
    const unsigned row0 = blockIdx.x * GBM;

    if (tid < OUT1) {
        float s = gamma[tid] * rsqrtf(var[tid] + 1e-5f);
        sS[tid] = s;
        sB[tid] = beta[tid] - mean[tid] * s;
    }
    __syncthreads();

    float c[2][6][4];
    #pragma unroll
    for (int mt = 0; mt < 2; mt++)
        #pragma unroll
        for (int nt = 0; nt < 6; nt++)
            #pragma unroll
            for (int q = 0; q < 4; q++) c[mt][nt][q] = 0.f;

    const int am = tid >> 2;
    const int akq = tid & 3;

    #pragma unroll
    for (int k0 = 0; k0 < OUT1; k0 += GBK) {
        {
            int kk = k0 + akq*4;
            unsigned base = (row0 + am)*OUT1 + kk;
            float4 p0 = *reinterpret_cast<const float4*>(&g_rp[base]);
            float4 p1 = *reinterpret_cast<const float4*>(&g_rp[(size_t)POSN*OUT1 + base]);
            float v[4] = {p0.x+p1.x, p0.y+p1.y, p0.z+p1.z, p0.w+p1.w};
            #pragma unroll
            for (int i = 0; i < 4; i++) {
                float r = fmaxf(fmaf(v[i], sS[kk+i], sB[kk+i]), 0.f);
                float h = __uint_as_float(f2tf32(r));
                A2h[akq*4 + i][am] = h;
                A2l[akq*4 + i][am] = __uint_as_float(f2tf32(r - h));
            }
        }
        {
            const unsigned base = (unsigned)k0 * N2;
            #pragma unroll
            for (int i = 0; i < 12; i++) {
                int idx = tid + (i << 8);
                int n = idx % N2, k = idx / N2;
                B2h[k][n] = g_w23h[base + idx];
                B2l[k][n] = g_w23l[base + idx];
            }
        }
        __syncthreads();

        #pragma unroll
        for (int ks = 0; ks < 2; ks++) {
            const int kb = ks * 8;
            uint32_t ah[2][4], al[2][4];
            #pragma unroll
            for (int mt = 0; mt < 2; mt++) {
                int mrow = wm*32 + mt*16 + ar;
                ah[mt][0] = __float_as_uint(A2h[kb+ac  ][mrow  ]);
                ah[mt][1] = __float_as_uint(A2h[kb+ac  ][mrow+8]);
                ah[mt][2] = __float_as_uint(A2h[kb+ac+4][mrow  ]);
                ah[mt][3] = __float_as_uint(A2h[kb+ac+4][mrow+8]);
                al[mt][0] = __float_as_uint(A2l[kb+ac  ][mrow  ]);
                al[mt][1] = __float_as_uint(A2l[kb+ac  ][mrow+8]);
                al[mt][2] = __float_as_uint(A2l[kb+ac+4][mrow  ]);
                al[mt][3] = __float_as_uint(A2l[kb+ac+4][mrow+8]);
            }
            uint32_t bh[6][2], bl[6][2];
            #pragma unroll
            for (int nt = 0; nt < 6; nt++) {
                int n = wn*48 + nt*8 + ar;
                bh[nt][0] = __float_as_uint(B2h[kb+ac  ][n]);
                bh[nt][1] = __float_as_uint(B2h[kb+ac+4][n]);
                bl[nt][0] = __float_as_uint(B2l[kb+ac  ][n]);
                bl[nt][1] = __float_as_uint(B2l[kb+ac+4][n]);
            }
            #pragma unroll
            for (int mt = 0; mt < 2; mt++)
                #pragma unroll
                for (int nt = 0; nt < 6; nt++) {
                    mma_tf32(c[mt][nt], ah[mt], bl[nt]);
                    mma_tf32(c[mt][nt], al[mt], bh[nt]);
                    mma_tf32(c[mt][nt], ah[mt], bh[nt]);
                }
        }
        __syncthreads();
    }

    #pragma unroll
    for (int nt = 0; nt < 6; nt++) {
        int n0 = wn*48 + nt*8 + 2*ac;
        float bias0 = (n0 < OUT1) ? b2[n0] : b3[n0 - OUT1];
        float bias1 = (n0 + 1 < OUT1) ? b2[n0 + 1] : b3[n0 + 1 - OUT1];
        #pragma unroll
        for (int mt = 0; mt < 2; mt++) {
            unsigned m0 = row0 + wm*32 + mt*16 + ar;
            *reinterpret_cast<float2*>(&g_wab[(size_t)m0*N2 + n0]) =
                make_float2(c[mt][nt][0] + bias0, c[mt][nt][1] + bias1);
            *reinterpret_cast<float2*>(&g_wab[(size_t)(m0+8)*N2 + n0]) =
                make_float2(c[mt][nt][2] + bias0, c[mt][nt][3] + bias1);
        }
    }
}

// ---------------------------------------------------------------------------
// K3: apply — R11 structure + vectorized float2 output stores
// ---------------------------------------------------------------------------
__global__ __launch_bounds__(128) void apply_kernel(
    const float* __restrict__ x, float* __restrict__ out)
{
    const int g = blockIdx.x, h2 = blockIdx.y, b = blockIdx.z;
    __shared__ float xs[GCD][3][3][58];
    __shared__ float wab[WD][12];
    __shared__ float sms[WD*37];

    const int tid = threadIdx.x;
    const unsigned posBase = (unsigned)(b*HD + h2)*WD;

    for (int it = tid; it < WD * 12; it += 128) {
        int q = it % 12;
        int w = it / 12;
        int col = (q < 6) ? (g*6 + q) : (OUT1 + g*6 + q - 6);
        wab[w][q] = g_wab[(size_t)(posBase + w)*N2 + col];
    }
    load_taps(x, b, g, h2, xs, tid);
    __syncthreads();

    for (int it = tid; it < WD * 4; it += 128) {
        int t = it % 4;
        int w = it / 4;
        int nh = t >> 1, nw = t & 1;
        float e[9], m = -1e30f;
        #pragma unroll
        for (int kk = 0; kk < 9; kk++) {
            int kh = kk / 3, kw = kk % 3;
            e[kk] = wab[w][kh*2 + nh] * wab[w][6 + kw*2 + nw];
            m = fmaxf(m, e[kk]);
        }
        float s = 0.f;
        #pragma unroll
        for (int kk = 0; kk < 9; kk++) { e[kk] = expf(e[kk] - m); s += e[kk]; }
        float inv = 1.f / (s * 9.f);
        #pragma unroll
        for (int kk = 0; kk < 9; kk++) sms[w*37 + t*9 + kk] = e[kk] * inv;
    }
    __syncthreads();

    const int jv0 = h2 % 3, jv1 = (56 + h2) % 3, jv2 = (112 + h2) % 3;
    const int jvv[3] = {jv0, jv1, jv2};

    for (int it = tid; it < GCD * WD; it += 128) {
        int w  = it % WD;
        int gc = it / WD;
        float o[4] = {0.f, 0.f, 0.f, 0.f};
        #pragma unroll
        for (int kk = 0; kk < 9; kk++) {
            int kh = kk / 3, kw = kk % 3;
            float u = xs[gc][kw][kh][w + jvv[kw]];
            #pragma unroll
            for (int t = 0; t < 4; t++)
                o[t] = fmaf(u, sms[w*37 + t*9 + kk], o[t]);
        }
        int c = g*GCD + gc;
        unsigned ob = ((unsigned)(b*CD + c))*OWD + 2*h2;
        // nh rows: (nw=0,1) contiguous -> coalesced float2 stores
        *reinterpret_cast<float2*>(&out[(size_t)ob*OWD + 2*w]) =
            make_float2(o[0], o[1]);
        *reinterpret_cast<float2*>(&out[(size_t)(ob+1)*OWD + 2*w]) =
            make_float2(o[2], o[3]);
    }
}

// ---------------------------------------------------------------------------
extern "C" void kernel_launch(void* const* d_in, const int* in_sizes, int n_in,
                              void* d_out, int out_size) {
    const float* x     = (const float*)d_in[0];
    const float* w1    = (const float*)d_in[1];
    const float* gamma = (const float*)d_in[2];
    const float* beta  = (const float*)d_in[3];
    const float* mean  = (const float*)d_in[4];
    const float* var   = (const float*)d_in[5];
    const float* w2    = (const float*)d_in[6];
    const float* b2    = (const float*)d_in[7];
    const float* w3    = (const float*)d_in[8];
    const float* b3    = (const float*)d_in[9];
    float* out = (float*)d_out;

    dim3 gridA(GD, HD, BD);   // (16, 56, 4)
    w1pack_kernel<<<((IN1/2)*OUT1 + 255)/256, 256>>>(w1);
    w23split_kernel<<<(OUT1*N2 + 255)/256, 256>>>(w2, w3);
    desc_kernel<<<gridA, 128>>>(x);
    gemm_tc_kernel<<<dim3(POSN / GBM, 2), 256>>>();
    gemm2_kernel<<<POSN / GBM, 256>>>(gamma, beta, mean, var, b2, b3);
    apply_kernel<<<gridA, 128>>>(x, out);
}

// round 15
// speedup vs baseline: 1.4608x; 1.4608x over previous
#include <cuda_runtime.h>
#include <cuda_bf16.h>
#include <cstdint>

#define BD 4
#define CD 256
#define HD 56
#define WD 56
#define GD 16
#define GCD 16
#define POSN (BD*HD*WD)   // 12544
#define IN1 2112
#define OUT1 96
#define OWD 112
#define KHALF 1056        // IN1/2 (k units)
#define N2 192

// Scratch (device globals)
__device__ float    g_desc[(size_t)IN1 * POSN];      // [feature][pos] ~106 MB
__device__ float    g_rp[2ull * POSN * OUT1];        // split-K partials (pre-BN)
__device__ uint32_t g_w1ph[(size_t)(IN1/2) * OUT1];  // bf16x2-packed hi, [kp][n]
__device__ uint32_t g_w1pl[(size_t)(IN1/2) * OUT1];  // bf16x2-packed lo residual
__device__ float    g_w23h[(size_t)OUT1 * N2];       // tf32 split for gemm2
__device__ float    g_w23l[(size_t)OUT1 * N2];
__device__ float    g_wab[(size_t)POSN * N2];        // wa | wb

// ---------------------------------------------------------------------------
// helpers
// ---------------------------------------------------------------------------
__device__ __forceinline__ uint32_t f2tf32(float f) {
    uint32_t r;
    asm("cvt.rna.tf32.f32 %0, %1;" : "=r"(r) : "f"(f));
    return r;
}
__device__ __forceinline__ void mma_tf32(float* c, const uint32_t* a, const uint32_t* b) {
    asm volatile(
        "mma.sync.aligned.m16n8k8.row.col.f32.tf32.tf32.f32 "
        "{%0,%1,%2,%3}, {%4,%5,%6,%7}, {%8,%9}, {%0,%1,%2,%3};"
        : "+f"(c[0]), "+f"(c[1]), "+f"(c[2]), "+f"(c[3])
        : "r"(a[0]), "r"(a[1]), "r"(a[2]), "r"(a[3]), "r"(b[0]), "r"(b[1]));
}
__device__ __forceinline__ void mma_bf16(float* c, const uint32_t* a, const uint32_t* b) {
    asm volatile(
        "mma.sync.aligned.m16n8k16.row.col.f32.bf16.bf16.f32 "
        "{%0,%1,%2,%3}, {%4,%5,%6,%7}, {%8,%9}, {%0,%1,%2,%3};"
        : "+f"(c[0]), "+f"(c[1]), "+f"(c[2]), "+f"(c[3])
        : "r"(a[0]), "r"(a[1]), "r"(a[2]), "r"(a[3]), "r"(b[0]), "r"(b[1]));
}
// pack k-pair: lo half = even k, hi half = odd k
__device__ __forceinline__ uint32_t packbf(float klo, float khi) {
    uint32_t r;
    asm("cvt.rn.bf16x2.f32 %0, %1, %2;" : "=r"(r) : "f"(khi), "f"(klo));
    return r;
}
__device__ __forceinline__ float bfround(float v) {
    return __bfloat162float(__float2bfloat16(v));
}

// ---------------------------------------------------------------------------
// K0a: pack w1 -> bf16x2 hi/lo, [kp][n]  (kp = k/2)
// ---------------------------------------------------------------------------
__global__ __launch_bounds__(256) void w1pack_kernel(const float* __restrict__ w1) {
    int idx = blockIdx.x * 256 + threadIdx.x;
    if (idx >= (IN1/2) * OUT1) return;
    int n  = idx % OUT1;
    int kp = idx / OUT1;
    float v0 = w1[(unsigned)n * IN1 + 2*kp];
    float v1 = w1[(unsigned)n * IN1 + 2*kp + 1];
    float h0 = bfround(v0), h1 = bfround(v1);
    g_w1ph[idx] = packbf(h0, h1);
    g_w1pl[idx] = packbf(v0 - h0, v1 - h1);
}

// ---------------------------------------------------------------------------
// K0b: pre-split [w2|w3] -> [k][n] tf32 hi/lo
// ---------------------------------------------------------------------------
__global__ __launch_bounds__(256) void w23split_kernel(
    const float* __restrict__ w2, const float* __restrict__ w3) {
    int idx = blockIdx.x * 256 + threadIdx.x;
    if (idx >= OUT1 * N2) return;
    int n = idx % N2;
    int k = idx / N2;
    float v = (n < OUT1) ? w2[(unsigned)n * OUT1 + k]
                         : w3[(unsigned)(n - OUT1) * OUT1 + k];
    float h = __uint_as_float(f2tf32(v));
    g_w23h[idx] = h;
    g_w23l[idx] = __uint_as_float(f2tf32(v - h));
}

// ---------------------------------------------------------------------------
// Scrambled-unfold taps (matches actual reference):
//   m = kw*56 + h2;  h = m/3;  j = m%3;  T = x[b,c,h+kh-1, w2+j-1] (0 pad)
// ---------------------------------------------------------------------------
__device__ __forceinline__ void load_taps(const float* __restrict__ x,
                                          int b, int g, int h2,
                                          float (*xs)[3][3][58], int tid) {
    const unsigned cbase = (unsigned)(b*CD + g*GCD);
    for (int idx = tid; idx < GCD * 9 * 58; idx += 128) {
        int wp = idx % 58;
        int t  = idx / 58;
        int kh = t % 3;
        int kw = (t / 3) % 3;
        int gc = t / 9;
        int m  = kw * 56 + h2;
        int hh = m / 3 + kh - 1;
        int ww = wp - 1;
        float v = 0.f;
        if (hh >= 0 && hh < HD && ww >= 0 && ww < WD)
            v = x[((cbase + gc)*HD + hh)*WD + ww];
        xs[gc][kw][kh][wp] = v;
    }
}

// ---------------------------------------------------------------------------
// K1: descriptor build (R11, proven)
// ---------------------------------------------------------------------------
__global__ __launch_bounds__(128) void desc_kernel(const float* __restrict__ x) {
    const int g = blockIdx.x, h2 = blockIdx.y, b = blockIdx.z;
    __shared__ float xs[GCD][3][3][58];

    const int tid = threadIdx.x;
    load_taps(x, b, g, h2, xs, tid);
    __syncthreads();

    const int jv0 = h2 % 3, jv1 = (56 + h2) % 3, jv2 = (112 + h2) % 3;
    const unsigned posBase = (unsigned)(b*HD + h2)*WD;

    for (int it = tid; it < GCD * WD; it += 128) {
        int w  = it % WD;
        int gc = it / WD;
        float T[3][3];
        #pragma unroll
        for (int kh = 0; kh < 3; kh++) {
            T[kh][0] = xs[gc][0][kh][w + jv0];
            T[kh][1] = xs[gc][1][kh][w + jv1];
            T[kh][2] = xs[gc][2][kh][w + jv2];
        }
        unsigned f2 = (unsigned)(576 + g*48 + gc*3);
        unsigned f3 = (unsigned)(1344 + g*48 + gc*3);
        #pragma unroll
        for (int kw = 0; kw < 3; kw++) {
            float m = fmaxf(T[0][kw], fmaxf(T[1][kw], T[2][kw]));
            g_desc[(f2 + kw)*POSN + posBase + w] = m;
        }
        #pragma unroll
        for (int kh = 0; kh < 3; kh++) {
            float m = fmaxf(T[kh][0], fmaxf(T[kh][1], T[kh][2]));
            g_desc[(f3 + kh)*POSN + posBase + w] = m;
        }
    }

    const int jvv[3] = {jv0, jv1, jv2};
    for (int it = tid; it < 4 * WD; it += 128) {
        int w  = it % WD;
        int jc = it / WD;
        unsigned f1 = (unsigned)(g*36 + jc*9);
        #pragma unroll
        for (int kh = 0; kh < 3; kh++) {
            #pragma unroll
            for (int kw = 0; kw < 3; kw++) {
                int wp = w + jvv[kw];
                float m = xs[jc][kw][kh][wp];
                m = fmaxf(m, xs[jc + 4 ][kw][kh][wp]);
                m = fmaxf(m, xs[jc + 8 ][kw][kh][wp]);
                m = fmaxf(m, xs[jc + 12][kw][kh][wp]);
                g_desc[(f1 + kh*3 + kw)*POSN + posBase + w] = m;
            }
        }
    }
}

// ---------------------------------------------------------------------------
// K2: GEMM1 3xBF16 m16n8k16 — EXACT R11 version (best measured: 81.5 us).
// BM=64, BN=96, tile = 8 kp (16 k). 256 threads = 8 warps (2m x 4n).
// ---------------------------------------------------------------------------
#define GBM 64
#define APR 72
#define BPR 104

__global__ __launch_bounds__(256) void gemm_tc_kernel() {
    __shared__ uint32_t Aph[8][APR], Apl[8][APR];
    __shared__ uint32_t Bph[8][BPR], Bpl[8][BPR];

    const int tid  = threadIdx.x;
    const int warp = tid >> 5;
    const int lane = tid & 31;
    const int wm = warp >> 2;          // 0..1 (m)
    const int wn = warp & 3;           // 0..3 (n)
    const int ar = lane >> 2;          // 0..7
    const int ac = lane & 3;           // 0..3
    const unsigned row0 = blockIdx.x * GBM;
    const int khalf = blockIdx.y;
    const unsigned kbase = khalf * KHALF;          // k units
    const unsigned kpbase = kbase >> 1;            // kp units

    float c[2][3][4];
    #pragma unroll
    for (int mt = 0; mt < 2; mt++)
        #pragma unroll
        for (int nt = 0; nt < 3; nt++)
            #pragma unroll
            for (int q = 0; q < 4; q++) c[mt][nt][q] = 0.f;

    const int akp = tid >> 5;          // 0..7 (kp row in tile)
    const int am2 = lane * 2;          // 0..62 (m pair)

    for (int k0 = 0; k0 < KHALF; k0 += 16) {
        // A tile: 16 k x 64 m -> bf16x2 k-pairs. Each thread: 2 float2 loads.
        {
            unsigned krow = kbase + k0 + 2*akp;
            float2 v0 = *reinterpret_cast<const float2*>(&g_desc[(size_t)krow*POSN + row0 + am2]);
            float2 v1 = *reinterpret_cast<const float2*>(&g_desc[(size_t)(krow+1)*POSN + row0 + am2]);
            float h00 = bfround(v0.x), h10 = bfround(v1.x);
            float h01 = bfround(v0.y), h11 = bfround(v1.y);
            *reinterpret_cast<uint2*>(&Aph[akp][am2]) =
                make_uint2(packbf(h00, h10), packbf(h01, h11));
            *reinterpret_cast<uint2*>(&Apl[akp][am2]) =
                make_uint2(packbf(v0.x - h00, v1.x - h10),
                           packbf(v0.y - h01, v1.y - h11));
        }
        // B tile: 8 kp x 96 n pre-packed, coalesced (768 u32 per array)
        {
            const unsigned base = (kpbase + (k0 >> 1)) * OUT1;
            #pragma unroll
            for (int i = 0; i < 3; i++) {
                int idx = tid + (i << 8);
                int n = idx % OUT1, kp = idx / OUT1;
                Bph[kp][n] = g_w1ph[base + idx];
                Bpl[kp][n] = g_w1pl[base + idx];
            }
        }
        __syncthreads();

        uint32_t ah[2][4], al[2][4];
        #pragma unroll
        for (int mt = 0; mt < 2; mt++) {
            int mrow = wm*32 + mt*16 + ar;
            ah[mt][0] = Aph[ac  ][mrow];   ah[mt][1] = Aph[ac  ][mrow+8];
            ah[mt][2] = Aph[ac+4][mrow];   ah[mt][3] = Aph[ac+4][mrow+8];
            al[mt][0] = Apl[ac  ][mrow];   al[mt][1] = Apl[ac  ][mrow+8];
            al[mt][2] = Apl[ac+4][mrow];   al[mt][3] = Apl[ac+4][mrow+8];
        }
        uint32_t bh[3][2], bl[3][2];
        #pragma unroll
        for (int nt = 0; nt < 3; nt++) {
            int n = wn*24 + nt*8 + ar;
            bh[nt][0] = Bph[ac][n];  bh[nt][1] = Bph[ac+4][n];
            bl[nt][0] = Bpl[ac][n];  bl[nt][1] = Bpl[ac+4][n];
        }
        #pragma unroll
        for (int mt = 0; mt < 2; mt++)
            #pragma unroll
            for (int nt = 0; nt < 3; nt++) {
                mma_bf16(c[mt][nt], ah[mt], bl[nt]);   // hi x lo
                mma_bf16(c[mt][nt], al[mt], bh[nt]);   // lo x hi
                mma_bf16(c[mt][nt], ah[mt], bh[nt]);   // hi x hi
            }
        __syncthreads();
    }

    float* rp = &g_rp[(size_t)khalf * POSN * OUT1];
    #pragma unroll
    for (int nt = 0; nt < 3; nt++) {
        int n0 = wn*24 + nt*8 + 2*ac;
        #pragma unroll
        for (int mt = 0; mt < 2; mt++) {
            unsigned m0 = row0 + wm*32 + mt*16 + ar;
            *reinterpret_cast<float2*>(&rp[m0*OUT1 + n0]) =
                make_float2(c[mt][nt][0], c[mt][nt][1]);
            *reinterpret_cast<float2*>(&rp[(m0+8)*OUT1 + n0]) =
                make_float2(c[mt][nt][2], c[mt][nt][3]);
        }
    }
}

// ---------------------------------------------------------------------------
// K2b: GEMM2 (tf32x3, R11): wab = relu(BN(rp0+rp1)) @ w23 + bias
// ---------------------------------------------------------------------------
#define GBK 16
#define A2STR 72
#define B2STR 200

__global__ __launch_bounds__(256) void gemm2_kernel(
    const float* __restrict__ gamma, const float* __restrict__ beta,
    const float* __restrict__ mean,  const float* __restrict__ var,
    const float* __restrict__ b2,    const float* __restrict__ b3)
{
    __shared__ float A2h[GBK][A2STR], A2l[GBK][A2STR];
    __shared__ float B2h[GBK][B2STR], B2l[GBK][B2STR];
    __shared__ float sS[OUT1], sB[OUT1];

    const int tid  = threadIdx.x;
    const int warp = tid >> 5;
    const int lane = tid & 31;
    const int wm = warp >> 2;
    const int wn = warp & 3;
    const int ar = lane >> 2;
    const int ac = lane & 3;
    const unsigned row0 = blockIdx.x * GBM;

    if (tid < OUT1) {
        float s = gamma[tid] * rsqrtf(var[tid] + 1e-5f);
        sS[tid] = s;
        sB[tid] = beta[tid] - mean[tid] * s;
    }
    __syncthreads();

    float c[2][6][4];
    #pragma unroll
    for (int mt = 0; mt < 2; mt++)
        #pragma unroll
        for (int nt = 0; nt < 6; nt++)
            #pragma unroll
            for (int q = 0; q < 4; q++) c[mt][nt][q] = 0.f;

    const int am = tid >> 2;
    const int akq = tid & 3;

    #pragma unroll
    for (int k0 = 0; k0 < OUT1; k0 += GBK) {
        {
            int kk = k0 + akq*4;
            unsigned base = (row0 + am)*OUT1 + kk;
            float4 p0 = *reinterpret_cast<const float4*>(&g_rp[base]);
            float4 p1 = *reinterpret_cast<const float4*>(&g_rp[(size_t)POSN*OUT1 + base]);
            float v[4] = {p0.x+p1.x, p0.y+p1.y, p0.z+p1.z, p0.w+p1.w};
            #pragma unroll
            for (int i = 0; i < 4; i++) {
                float r = fmaxf(fmaf(v[i], sS[kk+i], sB[kk+i]), 0.f);
                float h = __uint_as_float(f2tf32(r));
                A2h[akq*4 + i][am] = h;
                A2l[akq*4 + i][am] = __uint_as_float(f2tf32(r - h));
            }
        }
        {
            const unsigned base = (unsigned)k0 * N2;
            #pragma unroll
            for (int i = 0; i < 12; i++) {
                int idx = tid + (i << 8);
                int n = idx % N2, k = idx / N2;
                B2h[k][n] = g_w23h[base + idx];
                B2l[k][n] = g_w23l[base + idx];
            }
        }
        __syncthreads();

        #pragma unroll
        for (int ks = 0; ks < 2; ks++) {
            const int kb = ks * 8;
            uint32_t ah[2][4], al[2][4];
            #pragma unroll
            for (int mt = 0; mt < 2; mt++) {
                int mrow = wm*32 + mt*16 + ar;
                ah[mt][0] = __float_as_uint(A2h[kb+ac  ][mrow  ]);
                ah[mt][1] = __float_as_uint(A2h[kb+ac  ][mrow+8]);
                ah[mt][2] = __float_as_uint(A2h[kb+ac+4][mrow  ]);
                ah[mt][3] = __float_as_uint(A2h[kb+ac+4][mrow+8]);
                al[mt][0] = __float_as_uint(A2l[kb+ac  ][mrow  ]);
                al[mt][1] = __float_as_uint(A2l[kb+ac  ][mrow+8]);
                al[mt][2] = __float_as_uint(A2l[kb+ac+4][mrow  ]);
                al[mt][3] = __float_as_uint(A2l[kb+ac+4][mrow+8]);
            }
            uint32_t bh[6][2], bl[6][2];
            #pragma unroll
            for (int nt = 0; nt < 6; nt++) {
                int n = wn*48 + nt*8 + ar;
                bh[nt][0] = __float_as_uint(B2h[kb+ac  ][n]);
                bh[nt][1] = __float_as_uint(B2h[kb+ac+4][n]);
                bl[nt][0] = __float_as_uint(B2l[kb+ac  ][n]);
                bl[nt][1] = __float_as_uint(B2l[kb+ac+4][n]);
            }
            #pragma unroll
            for (int mt = 0; mt < 2; mt++)
                #pragma unroll
                for (int nt = 0; nt < 6; nt++) {
                    mma_tf32(c[mt][nt], ah[mt], bl[nt]);
                    mma_tf32(c[mt][nt], al[mt], bh[nt]);
                    mma_tf32(c[mt][nt], ah[mt], bh[nt]);
                }
        }
        __syncthreads();
    }

    #pragma unroll
    for (int nt = 0; nt < 6; nt++) {
        int n0 = wn*48 + nt*8 + 2*ac;
        float bias0 = (n0 < OUT1) ? b2[n0] : b3[n0 - OUT1];
        float bias1 = (n0 + 1 < OUT1) ? b2[n0 + 1] : b3[n0 + 1 - OUT1];
        #pragma unroll
        for (int mt = 0; mt < 2; mt++) {
            unsigned m0 = row0 + wm*32 + mt*16 + ar;
            *reinterpret_cast<float2*>(&g_wab[(size_t)m0*N2 + n0]) =
                make_float2(c[mt][nt][0] + bias0, c[mt][nt][1] + bias1);
            *reinterpret_cast<float2*>(&g_wab[(size_t)(m0+8)*N2 + n0]) =
                make_float2(c[mt][nt][2] + bias0, c[mt][nt][3] + bias1);
        }
    }
}

// ---------------------------------------------------------------------------
// K3: apply — R11 structure + vectorized float2 output stores
// (rel_err verified identical to scalar stores in R14)
// ---------------------------------------------------------------------------
__global__ __launch_bounds__(128) void apply_kernel(
    const float* __restrict__ x, float* __restrict__ out)
{
    const int g = blockIdx.x, h2 = blockIdx.y, b = blockIdx.z;
    __shared__ float xs[GCD][3][3][58];
    __shared__ float wab[WD][12];
    __shared__ float sms[WD*37];

    const int tid = threadIdx.x;
    const unsigned posBase = (unsigned)(b*HD + h2)*WD;

    for (int it = tid; it < WD * 12; it += 128) {
        int q = it % 12;
        int w = it / 12;
        int col = (q < 6) ? (g*6 + q) : (OUT1 + g*6 + q - 6);
        wab[w][q] = g_wab[(size_t)(posBase + w)*N2 + col];
    }
    load_taps(x, b, g, h2, xs, tid);
    __syncthreads();

    for (int it = tid; it < WD * 4; it += 128) {
        int t = it % 4;
        int w = it / 4;
        int nh = t >> 1, nw = t & 1;
        float e[9], m = -1e30f;
        #pragma unroll
        for (int kk = 0; kk < 9; kk++) {
            int kh = kk / 3, kw = kk % 3;
            e[kk] = wab[w][kh*2 + nh] * wab[w][6 + kw*2 + nw];
            m = fmaxf(m, e[kk]);
        }
        float s = 0.f;
        #pragma unroll
        for (int kk = 0; kk < 9; kk++) { e[kk] = expf(e[kk] - m); s += e[kk]; }
        float inv = 1.f / (s * 9.f);
        #pragma unroll
        for (int kk = 0; kk < 9; kk++) sms[w*37 + t*9 + kk] = e[kk] * inv;
    }
    __syncthreads();

    const int jv0 = h2 % 3, jv1 = (56 + h2) % 3, jv2 = (112 + h2) % 3;
    const int jvv[3] = {jv0, jv1, jv2};

    for (int it = tid; it < GCD * WD; it += 128) {
        int w  = it % WD;
        int gc = it / WD;
        float o[4] = {0.f, 0.f, 0.f, 0.f};
        #pragma unroll
        for (int kk = 0; kk < 9; kk++) {
            int kh = kk / 3, kw = kk % 3;
            float u = xs[gc][kw][kh][w + jvv[kw]];
            #pragma unroll
            for (int t = 0; t < 4; t++)
                o[t] = fmaf(u, sms[w*37 + t*9 + kk], o[t]);
        }
        int c = g*GCD + gc;
        unsigned ob = ((unsigned)(b*CD + c))*OWD + 2*h2;
        *reinterpret_cast<float2*>(&out[(size_t)ob*OWD + 2*w]) =
            make_float2(o[0], o[1]);
        *reinterpret_cast<float2*>(&out[(size_t)(ob+1)*OWD + 2*w]) =
            make_float2(o[2], o[3]);
    }
}

// ---------------------------------------------------------------------------
extern "C" void kernel_launch(void* const* d_in, const int* in_sizes, int n_in,
                              void* d_out, int out_size) {
    const float* x     = (const float*)d_in[0];
    const float* w1    = (const float*)d_in[1];
    const float* gamma = (const float*)d_in[2];
    const float* beta  = (const float*)d_in[3];
    const float* mean  = (const float*)d_in[4];
    const float* var   = (const float*)d_in[5];
    const float* w2    = (const float*)d_in[6];
    const float* b2    = (const float*)d_in[7];
    const float* w3    = (const float*)d_in[8];
    const float* b3    = (const float*)d_in[9];
    float* out = (float*)d_out;

    dim3 gridA(GD, HD, BD);   // (16, 56, 4)
    w1pack_kernel<<<((IN1/2)*OUT1 + 255)/256, 256>>>(w1);
    w23split_kernel<<<(OUT1*N2 + 255)/256, 256>>>(w2, w3);
    desc_kernel<<<gridA, 128>>>(x);
    gemm_tc_kernel<<<dim3(POSN / GBM, 2), 256>>>();
    gemm2_kernel<<<POSN / GBM, 256>>>(gamma, beta, mean, var, b2, b3);
    apply_kernel<<<gridA, 128>>>(x, out);
}

// round 16
// speedup vs baseline: 1.7548x; 1.2013x over previous
#include <cuda_runtime.h>
#include <cuda_bf16.h>
#include <cstdint>

#define BD 4
#define CD 256
#define HD 56
#define WD 56
#define GD 16
#define GCD 16
#define POSN (BD*HD*WD)   // 12544
#define IN1 2112
#define OUT1 96
#define OWD 112
#define KHALF 1056        // IN1/2 (k units)
#define N2 192

// Scratch (device globals)
__device__ float    g_desc[(size_t)IN1 * POSN];      // [feature][pos] ~106 MB
__device__ float    g_rp[2ull * POSN * OUT1];        // split-K partials (pre-BN)
__device__ uint32_t g_w1ph[(size_t)(IN1/2) * OUT1];  // bf16x2-packed hi, [kp][n]
__device__ uint32_t g_w1pl[(size_t)(IN1/2) * OUT1];  // bf16x2-packed lo residual
__device__ float    g_w23h[(size_t)OUT1 * N2];       // tf32 split for gemm2
__device__ float    g_w23l[(size_t)OUT1 * N2];
__device__ float    g_wab[(size_t)POSN * N2];        // wa | wb

// ---------------------------------------------------------------------------
// helpers
// ---------------------------------------------------------------------------
__device__ __forceinline__ uint32_t f2tf32(float f) {
    uint32_t r;
    asm("cvt.rna.tf32.f32 %0, %1;" : "=r"(r) : "f"(f));
    return r;
}
__device__ __forceinline__ void mma_tf32(float* c, const uint32_t* a, const uint32_t* b) {
    asm volatile(
        "mma.sync.aligned.m16n8k8.row.col.f32.tf32.tf32.f32 "
        "{%0,%1,%2,%3}, {%4,%5,%6,%7}, {%8,%9}, {%0,%1,%2,%3};"
        : "+f"(c[0]), "+f"(c[1]), "+f"(c[2]), "+f"(c[3])
        : "r"(a[0]), "r"(a[1]), "r"(a[2]), "r"(a[3]), "r"(b[0]), "r"(b[1]));
}
__device__ __forceinline__ void mma_bf16(float* c, const uint32_t* a, const uint32_t* b) {
    asm volatile(
        "mma.sync.aligned.m16n8k16.row.col.f32.bf16.bf16.f32 "
        "{%0,%1,%2,%3}, {%4,%5,%6,%7}, {%8,%9}, {%0,%1,%2,%3};"
        : "+f"(c[0]), "+f"(c[1]), "+f"(c[2]), "+f"(c[3])
        : "r"(a[0]), "r"(a[1]), "r"(a[2]), "r"(a[3]), "r"(b[0]), "r"(b[1]));
}
// pack k-pair: lo half = even k, hi half = odd k
__device__ __forceinline__ uint32_t packbf(float klo, float khi) {
    uint32_t r;
    asm("cvt.rn.bf16x2.f32 %0, %1, %2;" : "=r"(r) : "f"(khi), "f"(klo));
    return r;
}
__device__ __forceinline__ float bfround(float v) {
    return __bfloat162float(__float2bfloat16(v));
}

// ---------------------------------------------------------------------------
// K0a: pack w1 -> bf16x2 hi/lo, [kp][n]  (kp = k/2)
// ---------------------------------------------------------------------------
__global__ __launch_bounds__(256) void w1pack_kernel(const float* __restrict__ w1) {
    int idx = blockIdx.x * 256 + threadIdx.x;
    if (idx >= (IN1/2) * OUT1) return;
    int n  = idx % OUT1;
    int kp = idx / OUT1;
    float v0 = w1[(unsigned)n * IN1 + 2*kp];
    float v1 = w1[(unsigned)n * IN1 + 2*kp + 1];
    float h0 = bfround(v0), h1 = bfround(v1);
    g_w1ph[idx] = packbf(h0, h1);
    g_w1pl[idx] = packbf(v0 - h0, v1 - h1);
}

// ---------------------------------------------------------------------------
// K0b: pre-split [w2|w3] -> [k][n] tf32 hi/lo
// ---------------------------------------------------------------------------
__global__ __launch_bounds__(256) void w23split_kernel(
    const float* __restrict__ w2, const float* __restrict__ w3) {
    int idx = blockIdx.x * 256 + threadIdx.x;
    if (idx >= OUT1 * N2) return;
    int n = idx % N2;
    int k = idx / N2;
    float v = (n < OUT1) ? w2[(unsigned)n * OUT1 + k]
                         : w3[(unsigned)(n - OUT1) * OUT1 + k];
    float h = __uint_as_float(f2tf32(v));
    g_w23h[idx] = h;
    g_w23l[idx] = __uint_as_float(f2tf32(v - h));
}

// ---------------------------------------------------------------------------
// Scrambled-unfold taps (matches actual reference):
//   m = kw*56 + h2;  h = m/3;  j = m%3;  T = x[b,c,h+kh-1, w2+j-1] (0 pad)
// Rows padded to 64 so wp = idx & 63 (constant per thread at stride 128);
// wp in [56,64) yields ww >= 56 -> guarded to 0, harmless.
// ---------------------------------------------------------------------------
__device__ __forceinline__ void load_taps(const float* __restrict__ x,
                                          int b, int g, int h2,
                                          float (*xs)[3][3][64], int tid) {
    const unsigned cbase = (unsigned)(b*CD + g*GCD);
    const int wp = tid & 63;           // constant across iterations (stride 128)
    const int ww = wp - 1;
    const bool wok = (ww >= 0 && ww < WD);
    for (int t = tid >> 6; t < GCD * 9; t += 2) {
        int kh = t % 3;
        int kw = (t / 3) % 3;
        int gc = t / 9;
        int m  = kw * 56 + h2;
        int hh = m / 3 + kh - 1;
        float v = 0.f;
        if (wok && hh >= 0 && hh < HD)
            v = x[((cbase + gc)*HD + hh)*WD + ww];
        xs[gc][kw][kh][wp] = v;
    }
}

// ---------------------------------------------------------------------------
// K1: descriptor build (R11 logic, 64-padded tap rows)
// ---------------------------------------------------------------------------
__global__ __launch_bounds__(128) void desc_kernel(const float* __restrict__ x) {
    const int g = blockIdx.x, h2 = blockIdx.y, b = blockIdx.z;
    __shared__ float xs[GCD][3][3][64];   // 36864 B

    const int tid = threadIdx.x;
    load_taps(x, b, g, h2, xs, tid);
    __syncthreads();

    const int jv0 = h2 % 3, jv1 = (56 + h2) % 3, jv2 = (112 + h2) % 3;
    const unsigned posBase = (unsigned)(b*HD + h2)*WD;

    for (int it = tid; it < GCD * WD; it += 128) {
        int w  = it % WD;
        int gc = it / WD;
        float T[3][3];
        #pragma unroll
        for (int kh = 0; kh < 3; kh++) {
            T[kh][0] = xs[gc][0][kh][w + jv0];
            T[kh][1] = xs[gc][1][kh][w + jv1];
            T[kh][2] = xs[gc][2][kh][w + jv2];
        }
        unsigned f2 = (unsigned)(576 + g*48 + gc*3);
        unsigned f3 = (unsigned)(1344 + g*48 + gc*3);
        #pragma unroll
        for (int kw = 0; kw < 3; kw++) {
            float m = fmaxf(T[0][kw], fmaxf(T[1][kw], T[2][kw]));
            g_desc[(f2 + kw)*POSN + posBase + w] = m;
        }
        #pragma unroll
        for (int kh = 0; kh < 3; kh++) {
            float m = fmaxf(T[kh][0], fmaxf(T[kh][1], T[kh][2]));
            g_desc[(f3 + kh)*POSN + posBase + w] = m;
        }
    }

    const int jvv[3] = {jv0, jv1, jv2};
    for (int it = tid; it < 4 * WD; it += 128) {
        int w  = it % WD;
        int jc = it / WD;
        unsigned f1 = (unsigned)(g*36 + jc*9);
        #pragma unroll
        for (int kh = 0; kh < 3; kh++) {
            #pragma unroll
            for (int kw = 0; kw < 3; kw++) {
                int wp = w + jvv[kw];
                float m = xs[jc][kw][kh][wp];
                m = fmaxf(m, xs[jc + 4 ][kw][kh][wp]);
                m = fmaxf(m, xs[jc + 8 ][kw][kh][wp]);
                m = fmaxf(m, xs[jc + 12][kw][kh][wp]);
                g_desc[(f1 + kh*3 + kw)*POSN + posBase + w] = m;
            }
        }
    }
}

// ---------------------------------------------------------------------------
// K2: GEMM1 3xBF16 m16n8k16, K-tile widened to 32 k (16 kp) -> 33 iters,
// half the barriers of R15. BM=64, BN=96. 256 thr = 8 warps (2m x 4n).
// smem ~22.5 KB.
// ---------------------------------------------------------------------------
#define GBM 64
#define APR 72
#define BPR 104

__global__ __launch_bounds__(256) void gemm_tc_kernel() {
    __shared__ uint32_t Aph[16][APR], Apl[16][APR];   // 2*4608 B
    __shared__ uint32_t Bph[16][BPR], Bpl[16][BPR];   // 2*6656 B

    const int tid  = threadIdx.x;
    const int warp = tid >> 5;
    const int lane = tid & 31;
    const int wm = warp >> 2;          // 0..1 (m)
    const int wn = warp & 3;           // 0..3 (n)
    const int ar = lane >> 2;          // 0..7
    const int ac = lane & 3;           // 0..3
    const unsigned row0 = blockIdx.x * GBM;
    const int khalf = blockIdx.y;
    const unsigned kbase = khalf * KHALF;          // k units
    const unsigned kpbase = kbase >> 1;            // kp units

    float c[2][3][4];
    #pragma unroll
    for (int mt = 0; mt < 2; mt++)
        #pragma unroll
        for (int nt = 0; nt < 3; nt++)
            #pragma unroll
            for (int q = 0; q < 4; q++) c[mt][nt][q] = 0.f;

    const int akp = tid >> 5;          // 0..7; handles kp rows akp, akp+8
    const int am2 = lane * 2;          // 0..62 (m pair)

    for (int k0 = 0; k0 < KHALF; k0 += 32) {
        // A tile: 32 k x 64 m -> bf16x2 k-pairs. 2 kp rows per thread.
        #pragma unroll
        for (int r = 0; r < 2; r++) {
            int kpr = akp + r*8;       // 0..15
            unsigned krow = kbase + k0 + 2*kpr;
            float2 v0 = *reinterpret_cast<const float2*>(&g_desc[(size_t)krow*POSN + row0 + am2]);
            float2 v1 = *reinterpret_cast<const float2*>(&g_desc[(size_t)(krow+1)*POSN + row0 + am2]);
            float h00 = bfround(v0.x), h10 = bfround(v1.x);
            float h01 = bfround(v0.y), h11 = bfround(v1.y);
            *reinterpret_cast<uint2*>(&Aph[kpr][am2]) =
                make_uint2(packbf(h00, h10), packbf(h01, h11));
            *reinterpret_cast<uint2*>(&Apl[kpr][am2]) =
                make_uint2(packbf(v0.x - h00, v1.x - h10),
                           packbf(v0.y - h01, v1.y - h11));
        }
        // B tile: 16 kp x 96 n pre-packed (1536 u32 per array, 6 per thread)
        {
            const unsigned base = (kpbase + (k0 >> 1)) * OUT1;
            #pragma unroll
            for (int i = 0; i < 6; i++) {
                int idx = tid + (i << 8);
                int n = idx % OUT1, kp = idx / OUT1;
                Bph[kp][n] = g_w1ph[base + idx];
                Bpl[kp][n] = g_w1pl[base + idx];
            }
        }
        __syncthreads();

        #pragma unroll
        for (int ks = 0; ks < 2; ks++) {
            const int kb = ks * 8;
            uint32_t ah[2][4], al[2][4];
            #pragma unroll
            for (int mt = 0; mt < 2; mt++) {
                int mrow = wm*32 + mt*16 + ar;
                ah[mt][0] = Aph[kb+ac  ][mrow];   ah[mt][1] = Aph[kb+ac  ][mrow+8];
                ah[mt][2] = Aph[kb+ac+4][mrow];   ah[mt][3] = Aph[kb+ac+4][mrow+8];
                al[mt][0] = Apl[kb+ac  ][mrow];   al[mt][1] = Apl[kb+ac  ][mrow+8];
                al[mt][2] = Apl[kb+ac+4][mrow];   al[mt][3] = Apl[kb+ac+4][mrow+8];
            }
            uint32_t bh[3][2], bl[3][2];
            #pragma unroll
            for (int nt = 0; nt < 3; nt++) {
                int n = wn*24 + nt*8 + ar;
                bh[nt][0] = Bph[kb+ac][n];  bh[nt][1] = Bph[kb+ac+4][n];
                bl[nt][0] = Bpl[kb+ac][n];  bl[nt][1] = Bpl[kb+ac+4][n];
            }
            #pragma unroll
            for (int mt = 0; mt < 2; mt++)
                #pragma unroll
                for (int nt = 0; nt < 3; nt++) {
                    mma_bf16(c[mt][nt], ah[mt], bl[nt]);   // hi x lo
                    mma_bf16(c[mt][nt], al[mt], bh[nt]);   // lo x hi
                    mma_bf16(c[mt][nt], ah[mt], bh[nt]);   // hi x hi
                }
        }
        __syncthreads();
    }

    float* rp = &g_rp[(size_t)khalf * POSN * OUT1];
    #pragma unroll
    for (int nt = 0; nt < 3; nt++) {
        int n0 = wn*24 + nt*8 + 2*ac;
        #pragma unroll
        for (int mt = 0; mt < 2; mt++) {
            unsigned m0 = row0 + wm*32 + mt*16 + ar;
            *reinterpret_cast<float2*>(&rp[m0*OUT1 + n0]) =
                make_float2(c[mt][nt][0], c[mt][nt][1]);
            *reinterpret_cast<float2*>(&rp[(m0+8)*OUT1 + n0]) =
                make_float2(c[mt][nt][2], c[mt][nt][3]);
        }
    }
}

// ---------------------------------------------------------------------------
// K2b: GEMM2 (tf32x3, unchanged): wab = relu(BN(rp0+rp1)) @ w23 + bias
// ---------------------------------------------------------------------------
#define GBK 16
#define A2STR 72
#define B2STR 200

__global__ __launch_bounds__(256) void gemm2_kernel(
    const float* __restrict__ gamma, const float* __restrict__ beta,
    const float* __restrict__ mean,  const float* __restrict__ var,
    const float* __restrict__ b2,    const float* __restrict__ b3)
{
    __shared__ float A2h[GBK][A2STR], A2l[GBK][A2STR];
    __shared__ float B2h[GBK][B2STR], B2l[GBK][B2STR];
    __shared__ float sS[OUT1], sB[OUT1];

    const int tid  = threadIdx.x;
    const int warp = tid >> 5;
    const int lane = tid & 31;
    const int wm = warp >> 2;
    const int wn = warp & 3;
    const int ar = lane >> 2;
    const int ac = lane & 3;
    const unsigned row0 = blockIdx.x * GBM;

    if (tid < OUT1) {
        float s = gamma[tid] * rsqrtf(var[tid] + 1e-5f);
        sS[tid] = s;
        sB[tid] = beta[tid] - mean[tid] * s;
    }
    __syncthreads();

    float c[2][6][4];
    #pragma unroll
    for (int mt = 0; mt < 2; mt++)
        #pragma unroll
        for (int nt = 0; nt < 6; nt++)
            #pragma unroll
            for (int q = 0; q < 4; q++) c[mt][nt][q] = 0.f;

    const int am = tid >> 2;
    const int akq = tid & 3;

    #pragma unroll
    for (int k0 = 0; k0 < OUT1; k0 += GBK) {
        {
            int kk = k0 + akq*4;
            unsigned base = (row0 + am)*OUT1 + kk;
            float4 p0 = *reinterpret_cast<const float4*>(&g_rp[base]);
            float4 p1 = *reinterpret_cast<const float4*>(&g_rp[(size_t)POSN*OUT1 + base]);
            float v[4] = {p0.x+p1.x, p0.y+p1.y, p0.z+p1.z, p0.w+p1.w};
            #pragma unroll
            for (int i = 0; i < 4; i++) {
                float r = fmaxf(fmaf(v[i], sS[kk+i], sB[kk+i]), 0.f);
                float h = __uint_as_float(f2tf32(r));
                A2h[akq*4 + i][am] = h;
                A2l[akq*4 + i][am] = __uint_as_float(f2tf32(r - h));
            }
        }
        {
            const unsigned base = (unsigned)k0 * N2;
            #pragma unroll
            for (int i = 0; i < 12; i++) {
                int idx = tid + (i << 8);
                int n = idx % N2, k = idx / N2;
                B2h[k][n] = g_w23h[base + idx];
                B2l[k][n] = g_w23l[base + idx];
            }
        }
        __syncthreads();

        #pragma unroll
        for (int ks = 0; ks < 2; ks++) {
            const int kb = ks * 8;
            uint32_t ah[2][4], al[2][4];
            #pragma unroll
            for (int mt = 0; mt < 2; mt++) {
                int mrow = wm*32 + mt*16 + ar;
                ah[mt][0] = __float_as_uint(A2h[kb+ac  ][mrow  ]);
                ah[mt][1] = __float_as_uint(A2h[kb+ac  ][mrow+8]);
                ah[mt][2] = __float_as_uint(A2h[kb+ac+4][mrow  ]);
                ah[mt][3] = __float_as_uint(A2h[kb+ac+4][mrow+8]);
                al[mt][0] = __float_as_uint(A2l[kb+ac  ][mrow  ]);
                al[mt][1] = __float_as_uint(A2l[kb+ac  ][mrow+8]);
                al[mt][2] = __float_as_uint(A2l[kb+ac+4][mrow  ]);
                al[mt][3] = __float_as_uint(A2l[kb+ac+4][mrow+8]);
            }
            uint32_t bh[6][2], bl[6][2];
            #pragma unroll
            for (int nt = 0; nt < 6; nt++) {
                int n = wn*48 + nt*8 + ar;
                bh[nt][0] = __float_as_uint(B2h[kb+ac  ][n]);
                bh[nt][1] = __float_as_uint(B2h[kb+ac+4][n]);
                bl[nt][0] = __float_as_uint(B2l[kb+ac  ][n]);
                bl[nt][1] = __float_as_uint(B2l[kb+ac+4][n]);
            }
            #pragma unroll
            for (int mt = 0; mt < 2; mt++)
                #pragma unroll
                for (int nt = 0; nt < 6; nt++) {
                    mma_tf32(c[mt][nt], ah[mt], bl[nt]);
                    mma_tf32(c[mt][nt], al[mt], bh[nt]);
                    mma_tf32(c[mt][nt], ah[mt], bh[nt]);
                }
        }
        __syncthreads();
    }

    #pragma unroll
    for (int nt = 0; nt < 6; nt++) {
        int n0 = wn*48 + nt*8 + 2*ac;
        float bias0 = (n0 < OUT1) ? b2[n0] : b3[n0 - OUT1];
        float bias1 = (n0 + 1 < OUT1) ? b2[n0 + 1] : b3[n0 + 1 - OUT1];
        #pragma unroll
        for (int mt = 0; mt < 2; mt++) {
            unsigned m0 = row0 + wm*32 + mt*16 + ar;
            *reinterpret_cast<float2*>(&g_wab[(size_t)m0*N2 + n0]) =
                make_float2(c[mt][nt][0] + bias0, c[mt][nt][1] + bias1);
            *reinterpret_cast<float2*>(&g_wab[(size_t)(m0+8)*N2 + n0]) =
                make_float2(c[mt][nt][2] + bias0, c[mt][nt][3] + bias1);
        }
    }
}

// ---------------------------------------------------------------------------
// K3: apply — R15 structure, 64-padded tap rows, float2 output stores
// smem: 36864 + 2688 + 8288 = 47840 B (< 48 KB static limit)
// ---------------------------------------------------------------------------
__global__ __launch_bounds__(128) void apply_kernel(
    const float* __restrict__ x, float* __restrict__ out)
{
    const int g = blockIdx.x, h2 = blockIdx.y, b = blockIdx.z;
    __shared__ float xs[GCD][3][3][64];
    __shared__ float wab[WD][12];
    __shared__ float sms[WD*37];

    const int tid = threadIdx.x;
    const unsigned posBase = (unsigned)(b*HD + h2)*WD;

    for (int it = tid; it < WD * 12; it += 128) {
        int q = it % 12;
        int w = it / 12;
        int col = (q < 6) ? (g*6 + q) : (OUT1 + g*6 + q - 6);
        wab[w][q] = g_wab[(size_t)(posBase + w)*N2 + col];
    }
    load_taps(x, b, g, h2, xs, tid);
    __syncthreads();

    for (int it = tid; it < WD * 4; it += 128) {
        int t = it % 4;
        int w = it / 4;
        int nh = t >> 1, nw = t & 1;
        float e[9], m = -1e30f;
        #pragma unroll
        for (int kk = 0; kk < 9; kk++) {
            int kh = kk / 3, kw = kk % 3;
            e[kk] = wab[w][kh*2 + nh] * wab[w][6 + kw*2 + nw];
            m = fmaxf(m, e[kk]);
        }
        float s = 0.f;
        #pragma unroll
        for (int kk = 0; kk < 9; kk++) { e[kk] = expf(e[kk] - m); s += e[kk]; }
        float inv = 1.f / (s * 9.f);
        #pragma unroll
        for (int kk = 0; kk < 9; kk++) sms[w*37 + t*9 + kk] = e[kk] * inv;
    }
    __syncthreads();

    const int jv0 = h2 % 3, jv1 = (56 + h2) % 3, jv2 = (112 + h2) % 3;
    const int jvv[3] = {jv0, jv1, jv2};

    for (int it = tid; it < GCD * WD; it += 128) {
        int w  = it % WD;
        int gc = it / WD;
        float o[4] = {0.f, 0.f, 0.f, 0.f};
        #pragma unroll
        for (int kk = 0; kk < 9; kk++) {
            int kh = kk / 3, kw = kk % 3;
            float u = xs[gc][kw][kh][w + jvv[kw]];
            #pragma unroll
            for (int t = 0; t < 4; t++)
                o[t] = fmaf(u, sms[w*37 + t*9 + kk], o[t]);
        }
        int c = g*GCD + gc;
        unsigned ob = ((unsigned)(b*CD + c))*OWD + 2*h2;
        *reinterpret_cast<float2*>(&out[(size_t)ob*OWD + 2*w]) =
            make_float2(o[0], o[1]);
        *reinterpret_cast<float2*>(&out[(size_t)(ob+1)*OWD + 2*w]) =
            make_float2(o[2], o[3]);
    }
}

// ---------------------------------------------------------------------------
extern "C" void kernel_launch(void* const* d_in, const int* in_sizes, int n_in,
                              void* d_out, int out_size) {
    const float* x     = (const float*)d_in[0];
    const float* w1    = (const float*)d_in[1];
    const float* gamma = (const float*)d_in[2];
    const float* beta  = (const float*)d_in[3];
    const float* mean  = (const float*)d_in[4];
    const float* var   = (const float*)d_in[5];
    const float* w2    = (const float*)d_in[6];
    const float* b2    = (const float*)d_in[7];
    const float* w3    = (const float*)d_in[8];
    const float* b3    = (const float*)d_in[9];
    float* out = (float*)d_out;

    dim3 gridA(GD, HD, BD);   // (16, 56, 4)
    w1pack_kernel<<<((IN1/2)*OUT1 + 255)/256, 256>>>(w1);
    w23split_kernel<<<(OUT1*N2 + 255)/256, 256>>>(w2, w3);
    desc_kernel<<<gridA, 128>>>(x);
    gemm_tc_kernel<<<dim3(POSN / GBM, 2), 256>>>();
    gemm2_kernel<<<POSN / GBM, 256>>>(gamma, beta, mean, var, b2, b3);
    apply_kernel<<<gridA, 128>>>(x, out);
}